// round 13
// baseline (speedup 1.0000x reference)
#include <cuda_runtime.h>
#include <cuda_fp16.h>
#include <cstdint>

#define BATCH 8192
#define IN    2048
#define OUT   2048
#define P     8

#define BM 128
#define BN 256
#define BKC 128                // fp16 K per chunk (256 B rows, xor-swizzled)
#define NCHUNK (IN / BKC)      // 16
#define NSTAGE 2

#define NTHREADS 320           // 8 consumer warps + 2 producer warps (reg cap 204)

// prep grid split
#define SEL_BLOCKS 1024        // selector: one warp per sample (1024 x 8 warps)
#define WCV_BLOCKS 2048        // W -> fp16 conversion
#define PREP_BLOCKS (SEL_BLOCKS + WCV_BLOCKS)

// ---- dynamic shared memory layout ----
#define SM_RIDX   0            // 128 ints
#define SM_FULL   512          // 2 x 8B mbarriers
#define SM_EMPTY  576          // 2 x 8B mbarriers
#define SM_TILE   1024
#define OFF_A     0            // 128 rows x 256B = 32 KB
#define OFF_B     32768        // 256 rows x 256B = 64 KB
#define STAGE_BYTES 98304      // 96 KB per stage
#define SMEM_TOTAL (SM_TILE + NSTAGE * STAGE_BYTES)   // 197632 B

// ---------------- device scratch (no allocations allowed) ----------------
__device__ int  g_cnt[P];
__device__ int  g_list[P][BATCH];
__device__ int4 g_sel[BATCH];                      // e1,p1,e2,p2 per sample
__device__ __half g_xh[(size_t)BATCH * IN];        // 32 MB
__device__ __half g_wh[(size_t)P * OUT * IN];      // 64 MB
__device__ __half g_yh[(size_t)P * BATCH * OUT];   // 268 MB: 0.5*(y + b_e), fp16

// ---------------- helpers ----------------
__device__ __forceinline__ uint32_t smem_u32(const void* p) {
    uint32_t a;
    asm("{ .reg .u64 t; cvta.to.shared.u64 t, %1; cvt.u32.u64 %0, t; }"
        : "=r"(a) : "l"(p));
    return a;
}

__device__ __forceinline__ void cp16(uint32_t dst, const void* src, int sz) {
    asm volatile("cp.async.cg.shared.global [%0], [%1], 16, %2;"
                 :: "r"(dst), "l"(src), "r"(sz));
}

__device__ __forceinline__ void ldsm4(uint32_t* r, uint32_t addr) {
    asm volatile("ldmatrix.sync.aligned.m8n8.x4.shared.b16 {%0,%1,%2,%3}, [%4];"
                 : "=r"(r[0]), "=r"(r[1]), "=r"(r[2]), "=r"(r[3]) : "r"(addr));
}

__device__ __forceinline__ void mma16816(float* c, const uint32_t* a, const uint32_t* b) {
    asm volatile(
        "mma.sync.aligned.m16n8k16.row.col.f32.f16.f16.f32 "
        "{%0,%1,%2,%3}, {%4,%5,%6,%7}, {%8,%9}, {%0,%1,%2,%3};"
        : "+f"(c[0]), "+f"(c[1]), "+f"(c[2]), "+f"(c[3])
        : "r"(a[0]), "r"(a[1]), "r"(a[2]), "r"(a[3]), "r"(b[0]), "r"(b[1]));
}

#define MBAR_INIT(addr, cnt) \
    asm volatile("mbarrier.init.shared.b64 [%0], %1;" :: "r"(addr), "r"(cnt) : "memory")

#define MBAR_ARRIVE(addr) \
    asm volatile("mbarrier.arrive.shared.b64 _, [%0];" :: "r"(addr) : "memory")

#define CPASYNC_MBAR_ARRIVE(addr) \
    asm volatile("cp.async.mbarrier.arrive.noinc.shared.b64 [%0];" :: "r"(addr) : "memory")

#define MBAR_WAIT(addr, parity) do {                                              \
    asm volatile(                                                                 \
        "{\n\t.reg .pred P1;\n\t"                                                 \
        "WAIT_%=:\n\t"                                                            \
        "mbarrier.try_wait.parity.acquire.cta.shared::cta.b64 P1, [%0], %1, 0x989680;\n\t" \
        "@P1 bra.uni DONE_%=;\n\t"                                                \
        "bra.uni WAIT_%=;\n\t"                                                    \
        "DONE_%=:\n\t}"                                                           \
        :: "r"(addr), "r"(parity) : "memory");                                    \
} while (0)

// swizzled byte offset inside a [rows][256B] tile. chunk = 16B unit index
// (0..15). xor only touches the low 3 bits (row&7 <= 7) -> conflict-free
// ldmatrix (8 lanes hit banks 0,4,...,28) and intact bit 3.
__device__ __forceinline__ uint32_t sw_off(int row, int chunk) {
    return (uint32_t)(row * 256 + ((chunk ^ (row & 7)) << 4));
}

// ---------------------------------------------------------------------------
// Merged prep kernel: blocks [0, SEL_BLOCKS) run the selector with one warp
// per sample; blocks [SEL_BLOCKS, PREP_BLOCKS) convert W to fp16.
__global__ void prep_kernel(const float* __restrict__ x,
                            const float* __restrict__ W,
                            const float* __restrict__ Ws,
                            const float* __restrict__ bs) {
    if (blockIdx.x >= SEL_BLOCKS) {
        // ---- W -> fp16 ----
        const int bid = blockIdx.x - SEL_BLOCKS;
        size_t n4 = (size_t)P * OUT * IN / 4;
        size_t stride = (size_t)WCV_BLOCKS * blockDim.x;
        for (size_t i = (size_t)bid * blockDim.x + threadIdx.x; i < n4; i += stride) {
            float4 v = ((const float4*)W)[i];
            ((__half2*)g_wh)[2 * i]     = __floats2half2_rn(v.x, v.y);
            ((__half2*)g_wh)[2 * i + 1] = __floats2half2_rn(v.z, v.w);
        }
        return;
    }
    // ---- selector: top-2 of logits (softmax monotone -> skip), 1 warp/sample
    const int warp = threadIdx.x >> 5;
    const int lane = threadIdx.x & 31;
    const int s = blockIdx.x * (blockDim.x >> 5) + warp;   // 0..8191

    const float4* xr = (const float4*)(x + (size_t)s * IN);
    __half2* xh = (__half2*)(g_xh + (size_t)s * IN);
    float acc[P];
#pragma unroll
    for (int p = 0; p < P; p++) acc[p] = 0.f;
#pragma unroll
    for (int it = 0; it < IN / 128; it++) {            // 16 iterations
        const int k4 = it * 32 + lane;
        float4 xv = xr[k4];
        xh[2 * k4]     = __floats2half2_rn(xv.x, xv.y);
        xh[2 * k4 + 1] = __floats2half2_rn(xv.z, xv.w);
#pragma unroll
        for (int p = 0; p < P; p++) {
            float4 wv = ((const float4*)(Ws + (size_t)p * IN))[k4];
            acc[p] += xv.x * wv.x + xv.y * wv.y + xv.z * wv.z + xv.w * wv.w;
        }
    }
#pragma unroll
    for (int p = 0; p < P; p++) {
#pragma unroll
        for (int off = 16; off; off >>= 1)
            acc[p] += __shfl_xor_sync(0xffffffffu, acc[p], off);
    }
    if (lane == 0) {
        float best = -1e30f; int e1 = 0;
#pragma unroll
        for (int p = 0; p < P; p++) {
            float v = acc[p] + bs[p];
            acc[p] = v;
            if (v > best) { best = v; e1 = p; }
        }
        float sec = -1e30f; int e2 = 0;
#pragma unroll
        for (int p = 0; p < P; p++)
            if (p != e1 && acc[p] > sec) { sec = acc[p]; e2 = p; }
        int p1 = atomicAdd(&g_cnt[e1], 1);
        g_list[e1][p1] = s;
        int p2 = atomicAdd(&g_cnt[e2], 1);
        g_list[e2][p2] = s;
        g_sel[s] = make_int4(e1, p1, e2, p2);
    }
}

// ---------------------------------------------------------------------------
// Warp-specialized grouped gather-GEMM, single-pass fp16 mma.sync (fp32 acc).
// 8 consumer warps (64x64 tiles of 128x256) + 2 producer warps. K-chunk 128
// (16 chunks -> 16 barrier boundaries instead of 32), 2-stage mbarrier ring.
// A fragments double-buffered across k-steps. Epilogue stores 0.5*(y + b_e)
// as fp16 to compacted scratch (proven r11 form).
// ---------------------------------------------------------------------------
__global__ __launch_bounds__(NTHREADS, 1)
void moe_gemm_kernel(const float* __restrict__ bias) {
    const int e = blockIdx.z;
    const int n_rows = g_cnt[e];
    const int row0 = blockIdx.y * BM;
    if (row0 >= n_rows) return;
    const int col0 = blockIdx.x * BN;

    extern __shared__ char smem[];
    const uint32_t sb = smem_u32(smem);
    int* ridx = (int*)(smem + SM_RIDX);
    const int tid = threadIdx.x;
    const int lane = tid & 31;
    const int wid = tid >> 5;

    if (tid == 0) {
#pragma unroll
        for (int s = 0; s < NSTAGE; s++) {
            MBAR_INIT(sb + SM_FULL + 8 * s, 64);   // 64 producer lanes
            MBAR_INIT(sb + SM_EMPTY + 8 * s, 8);   // 8 consumer warps
        }
    }
    if (tid < BM) {
        int r = row0 + tid;
        ridx[tid] = (r < n_rows) ? g_list[e][r] : -1;
    }
    __syncthreads();

    const __half* wh = g_wh + (size_t)e * OUT * IN;

    if (wid >= 8) {
        // ------------------- 2 producer warps -------------------
        const int plane = (wid - 8) * 32 + lane;   // 0..63
        const int ck = plane & 15;                 // 16B chunk in 256B row
        const int rg = plane >> 4;                 // 0..3
        int ph_empty[NSTAGE] = {0, 0};
        for (int c = 0; c < NCHUNK; c++) {
            const int st = c & (NSTAGE - 1);
            if (c >= NSTAGE) {
                MBAR_WAIT(sb + SM_EMPTY + 8 * st, ph_empty[st]);
                ph_empty[st] ^= 1;
            }
            const int k0 = c * BKC;
            const uint32_t stage = sb + SM_TILE + st * STAGE_BYTES;
            // A: 128 gathered rows, 32 per lane
#pragma unroll 8
            for (int i = 0; i < 32; i++) {
                const int m = i * 4 + rg;
                const int r = ridx[m];
                const size_t off = ((size_t)(r < 0 ? 0 : r) * IN + k0) * 2 + ck * 16;
                cp16(stage + OFF_A + sw_off(m, ck), (const char*)g_xh + off,
                     (r >= 0) ? 16 : 0);
            }
            // B: 256 contiguous rows, 64 per lane
#pragma unroll 8
            for (int i = 0; i < 64; i++) {
                const int n = i * 4 + rg;
                const size_t off = ((size_t)(col0 + n) * IN + k0) * 2 + ck * 16;
                cp16(stage + OFF_B + sw_off(n, ck), (const char*)wh + off, 16);
            }
            CPASYNC_MBAR_ARRIVE(sb + SM_FULL + 8 * st);
        }
        return;
    }

    // ------------------- consumer warps -------------------
    const int wm = wid & 1;      // m group: rows wm*64 .. wm*64+63
    const int wn = wid >> 1;     // n group: cols wn*64 .. wn*64+63

    float acc[4][8][4];
#pragma unroll
    for (int i = 0; i < 4; i++)
#pragma unroll
        for (int j = 0; j < 8; j++)
#pragma unroll
            for (int k = 0; k < 4; k++) acc[i][j][k] = 0.f;

    const int a_r = lane & 15;
    const int a_c = lane >> 4;
    const int b_r = ((lane >> 4) & 1) * 8 + (lane & 7);
    const int b_c = (lane >> 3) & 1;

    const int a_row0 = wm * 64 + a_r;
    const int b_row0 = wn * 64 + b_r;

    int ph_full[NSTAGE] = {0, 0};
    for (int c = 0; c < NCHUNK; c++) {
        const int st = c & (NSTAGE - 1);
        MBAR_WAIT(sb + SM_FULL + 8 * st, ph_full[st]);
        ph_full[st] ^= 1;

        const uint32_t stage = sb + SM_TILE + st * STAGE_BYTES;

        uint32_t ah[2][4][4];
        // preload A fragments for ks=0
#pragma unroll
        for (int i = 0; i < 4; i++)
            ldsm4(ah[0][i], stage + OFF_A + sw_off(a_row0 + i * 16, a_c));

#pragma unroll
        for (int ks = 0; ks < BKC / 16; ks++) {      // 8 k-steps
            const int cur = ks & 1, nxt = cur ^ 1;
            // prefetch next ks's A fragments (issue under this ks's MMAs)
            if (ks < BKC / 16 - 1) {
#pragma unroll
                for (int i = 0; i < 4; i++)
                    ldsm4(ah[nxt][i],
                          stage + OFF_A + sw_off(a_row0 + i * 16, 2 * (ks + 1) + a_c));
            }
#pragma unroll
            for (int g = 0; g < 4; g++) {
                uint32_t bf[4];
                ldsm4(bf, stage + OFF_B + sw_off(b_row0 + g * 16, 2 * ks + b_c));
#pragma unroll
                for (int i = 0; i < 4; i++) {
                    mma16816(acc[i][2 * g],     ah[cur][i], &bf[0]);
                    mma16816(acc[i][2 * g + 1], ah[cur][i], &bf[2]);
                }
            }
        }
        __syncwarp();
        if (lane == 0) MBAR_ARRIVE(sb + SM_EMPTY + 8 * st);
    }

    // epilogue: store 0.5*(y + b_e) as fp16 to compacted scratch
    const float* bb = bias + (size_t)e * OUT + col0 + wn * 64 + 2 * (lane & 3);
#pragma unroll
    for (int i = 0; i < 4; i++) {
        int mbase = wm * 64 + i * 16 + (lane >> 2);
#pragma unroll
        for (int half = 0; half < 2; half++) {
            int mloc = mbase + half * 8;
            if (row0 + mloc < n_rows) {
                __half* yrow = g_yh + ((size_t)e * BATCH + row0 + mloc) * OUT
                             + col0 + wn * 64 + 2 * (lane & 3);
#pragma unroll
                for (int g = 0; g < 8; g++) {
                    float2 bv = *(const float2*)(bb + 8 * g);
                    __half2 h = __floats2half2_rn(
                        0.5f * (acc[i][g][2 * half] + bv.x),
                        0.5f * (acc[i][g][2 * half + 1] + bv.y));
                    *(__half2*)(yrow + 8 * g) = h;
                }
            }
        }
    }
}

// Combine: out[s] = yh[e1][p1] + yh[e2][p2]  (each already 0.5*(y+b)).
__global__ void combine_kernel(float* __restrict__ out) {
    const int s = blockIdx.x;
    const int4 sel = g_sel[s];
    const uint4* y1 = (const uint4*)(g_yh + ((size_t)sel.x * BATCH + sel.y) * OUT);
    const uint4* y2 = (const uint4*)(g_yh + ((size_t)sel.z * BATCH + sel.w) * OUT);
    float4* o = (float4*)(out + (size_t)s * OUT);
    const int i = threadIdx.x;           // 256 threads, OUT/8 = 256 groups of 8
    uint4 a = y1[i];
    uint4 b = y2[i];
    float4 r0, r1;
    {
        float2 fa = __half22float2(*(__half2*)&a.x), fb = __half22float2(*(__half2*)&b.x);
        r0.x = fa.x + fb.x; r0.y = fa.y + fb.y;
        fa = __half22float2(*(__half2*)&a.y); fb = __half22float2(*(__half2*)&b.y);
        r0.z = fa.x + fb.x; r0.w = fa.y + fb.y;
        fa = __half22float2(*(__half2*)&a.z); fb = __half22float2(*(__half2*)&b.z);
        r1.x = fa.x + fb.x; r1.y = fa.y + fb.y;
        fa = __half22float2(*(__half2*)&a.w); fb = __half22float2(*(__half2*)&b.w);
        r1.z = fa.x + fb.x; r1.w = fa.y + fb.y;
    }
    o[2 * i]     = r0;
    o[2 * i + 1] = r1;
}

// ---------------------------------------------------------------------------
extern "C" void kernel_launch(void* const* d_in, const int* in_sizes, int n_in,
                              void* d_out, int out_size) {
    const float* x  = (const float*)d_in[0];
    const float* W  = (const float*)d_in[1];
    const float* b  = (const float*)d_in[2];
    const float* Ws = (const float*)d_in[3];
    const float* bs = (const float*)d_in[4];
    float* out = (float*)d_out;

    static void* cnt_addr = nullptr;
    static bool attr_set = false;
    if (!attr_set) {
        cudaFuncSetAttribute(moe_gemm_kernel,
                             cudaFuncAttributeMaxDynamicSharedMemorySize, SMEM_TOTAL);
        cudaGetSymbolAddress(&cnt_addr, g_cnt);
        attr_set = true;
    }

    cudaMemsetAsync(cnt_addr, 0, P * sizeof(int));
    prep_kernel<<<PREP_BLOCKS, 256>>>(x, W, Ws, bs);   // selector + W conversion

    dim3 grid(OUT / BN, BATCH / BM, P);                // (8, 64, 8)
    moe_gemm_kernel<<<grid, NTHREADS, SMEM_TOTAL>>>(b);

    combine_kernel<<<BATCH, 256>>>(out);
}

// round 14
// speedup vs baseline: 1.0545x; 1.0545x over previous
#include <cuda_runtime.h>
#include <cuda_fp16.h>
#include <cstdint>

#define BATCH 8192
#define IN    2048
#define OUT   2048
#define P     8

#define BM 128
#define BN 256
#define BKC 64                 // fp16 K per chunk (128 B rows, xor-swizzled)
#define NCHUNK (IN / BKC)      // 32
#define NSTAGE 4

#define NTHREADS 320           // 8 consumer warps + 2 producer warps (reg cap 204)

// prep grid split
#define SEL_BLOCKS 1024        // selector: one warp per sample (1024 x 8 warps)
#define PREP_BLOCKS 3072       // all blocks join W->fp16 conversion

// ---- dynamic shared memory layout ----
#define SM_RIDX   0            // 128 ints
#define SM_FULL   512          // 4 x 8B mbarriers
#define SM_EMPTY  576          // 4 x 8B mbarriers
#define SM_TILE   1024
#define OFF_A     0            // 128 rows x 128B = 16 KB
#define OFF_B     16384        // 256 rows x 128B = 32 KB
#define STAGE_BYTES 49152      // 48 KB per stage
#define SMEM_TOTAL (SM_TILE + NSTAGE * STAGE_BYTES)   // 197632 B

// ---------------- device scratch (no allocations allowed) ----------------
__device__ int  g_cnt[P];
__device__ int  g_list[P][BATCH];
__device__ int4 g_sel[BATCH];                      // e1,p1,e2,p2 per sample
__device__ __half g_xh[(size_t)BATCH * IN];        // 32 MB
__device__ __half g_wh[(size_t)P * OUT * IN];      // 64 MB
__device__ __half g_yh[(size_t)P * BATCH * OUT];   // 268 MB: 0.5*(y + b_e), fp16

// ---------------- helpers ----------------
__device__ __forceinline__ uint32_t smem_u32(const void* p) {
    uint32_t a;
    asm("{ .reg .u64 t; cvta.to.shared.u64 t, %1; cvt.u32.u64 %0, t; }"
        : "=r"(a) : "l"(p));
    return a;
}

__device__ __forceinline__ void cp16(uint32_t dst, const void* src, int sz) {
    asm volatile("cp.async.cg.shared.global [%0], [%1], 16, %2;"
                 :: "r"(dst), "l"(src), "r"(sz));
}

__device__ __forceinline__ void ldsm4(uint32_t* r, uint32_t addr) {
    asm volatile("ldmatrix.sync.aligned.m8n8.x4.shared.b16 {%0,%1,%2,%3}, [%4];"
                 : "=r"(r[0]), "=r"(r[1]), "=r"(r[2]), "=r"(r[3]) : "r"(addr));
}

__device__ __forceinline__ void mma16816(float* c, const uint32_t* a, const uint32_t* b) {
    asm volatile(
        "mma.sync.aligned.m16n8k16.row.col.f32.f16.f16.f32 "
        "{%0,%1,%2,%3}, {%4,%5,%6,%7}, {%8,%9}, {%0,%1,%2,%3};"
        : "+f"(c[0]), "+f"(c[1]), "+f"(c[2]), "+f"(c[3])
        : "r"(a[0]), "r"(a[1]), "r"(a[2]), "r"(a[3]), "r"(b[0]), "r"(b[1]));
}

#define MBAR_INIT(addr, cnt) \
    asm volatile("mbarrier.init.shared.b64 [%0], %1;" :: "r"(addr), "r"(cnt) : "memory")

#define MBAR_ARRIVE(addr) \
    asm volatile("mbarrier.arrive.shared.b64 _, [%0];" :: "r"(addr) : "memory")

#define CPASYNC_MBAR_ARRIVE(addr) \
    asm volatile("cp.async.mbarrier.arrive.noinc.shared.b64 [%0];" :: "r"(addr) : "memory")

#define MBAR_WAIT(addr, parity) do {                                              \
    asm volatile(                                                                 \
        "{\n\t.reg .pred P1;\n\t"                                                 \
        "WAIT_%=:\n\t"                                                            \
        "mbarrier.try_wait.parity.acquire.cta.shared::cta.b64 P1, [%0], %1, 0x989680;\n\t" \
        "@P1 bra.uni DONE_%=;\n\t"                                                \
        "bra.uni WAIT_%=;\n\t"                                                    \
        "DONE_%=:\n\t}"                                                           \
        :: "r"(addr), "r"(parity) : "memory");                                    \
} while (0)

// swizzled byte offset inside a [rows][128B] tile: 16B chunk index XOR (row & 7)
__device__ __forceinline__ uint32_t sw_off(int row, int chunk) {
    return (uint32_t)(row * 128 + ((chunk ^ (row & 7)) << 4));
}

// ---------------------------------------------------------------------------
// Merged prep kernel. Blocks [0, SEL_BLOCKS) first run the selector (one warp
// per sample), then ALL PREP_BLOCKS blocks join the W->fp16 grid-stride loop,
// so the dominant 384 MB conversion stream is shared by 1.5x the blocks.
__global__ void prep_kernel(const float* __restrict__ x,
                            const float* __restrict__ W,
                            const float* __restrict__ Ws,
                            const float* __restrict__ bs) {
    if (blockIdx.x < SEL_BLOCKS) {
        // ---- selector: top-2 of logits (softmax monotone -> skip) ----
        const int warp = threadIdx.x >> 5;
        const int lane = threadIdx.x & 31;
        const int s = blockIdx.x * (blockDim.x >> 5) + warp;   // 0..8191

        const float4* xr = (const float4*)(x + (size_t)s * IN);
        __half2* xh = (__half2*)(g_xh + (size_t)s * IN);
        float acc[P];
#pragma unroll
        for (int p = 0; p < P; p++) acc[p] = 0.f;
#pragma unroll
        for (int it = 0; it < IN / 128; it++) {            // 16 iterations
            const int k4 = it * 32 + lane;
            float4 xv = xr[k4];
            xh[2 * k4]     = __floats2half2_rn(xv.x, xv.y);
            xh[2 * k4 + 1] = __floats2half2_rn(xv.z, xv.w);
#pragma unroll
            for (int p = 0; p < P; p++) {
                float4 wv = ((const float4*)(Ws + (size_t)p * IN))[k4];
                acc[p] += xv.x * wv.x + xv.y * wv.y + xv.z * wv.z + xv.w * wv.w;
            }
        }
#pragma unroll
        for (int p = 0; p < P; p++) {
#pragma unroll
            for (int off = 16; off; off >>= 1)
                acc[p] += __shfl_xor_sync(0xffffffffu, acc[p], off);
        }
        if (lane == 0) {
            float best = -1e30f; int e1 = 0;
#pragma unroll
            for (int p = 0; p < P; p++) {
                float v = acc[p] + bs[p];
                acc[p] = v;
                if (v > best) { best = v; e1 = p; }
            }
            float sec = -1e30f; int e2 = 0;
#pragma unroll
            for (int p = 0; p < P; p++)
                if (p != e1 && acc[p] > sec) { sec = acc[p]; e2 = p; }
            int p1 = atomicAdd(&g_cnt[e1], 1);
            g_list[e1][p1] = s;
            int p2 = atomicAdd(&g_cnt[e2], 1);
            g_list[e2][p2] = s;
            g_sel[s] = make_int4(e1, p1, e2, p2);
        }
    }

    // ---- W -> fp16: all blocks participate ----
    size_t n4 = (size_t)P * OUT * IN / 4;
    size_t stride = (size_t)PREP_BLOCKS * blockDim.x;
    for (size_t i = (size_t)blockIdx.x * blockDim.x + threadIdx.x; i < n4; i += stride) {
        float4 v = ((const float4*)W)[i];
        ((__half2*)g_wh)[2 * i]     = __floats2half2_rn(v.x, v.y);
        ((__half2*)g_wh)[2 * i + 1] = __floats2half2_rn(v.z, v.w);
    }
}

// ---------------------------------------------------------------------------
// Warp-specialized grouped gather-GEMM, single-pass fp16 mma.sync (fp32 acc).
// 8 consumer warps (64x64 tiles of 128x256) + 2 producer warps. 4-stage
// mbarrier ring; A fragments double-buffered across k-steps. This is the
// proven r11 configuration (440us best) — mainloop frozen.
// ---------------------------------------------------------------------------
__global__ __launch_bounds__(NTHREADS, 1)
void moe_gemm_kernel(const float* __restrict__ bias) {
    const int e = blockIdx.z;
    const int n_rows = g_cnt[e];
    const int row0 = blockIdx.y * BM;
    if (row0 >= n_rows) return;
    const int col0 = blockIdx.x * BN;

    extern __shared__ char smem[];
    const uint32_t sb = smem_u32(smem);
    int* ridx = (int*)(smem + SM_RIDX);
    const int tid = threadIdx.x;
    const int lane = tid & 31;
    const int wid = tid >> 5;

    if (tid == 0) {
#pragma unroll
        for (int s = 0; s < NSTAGE; s++) {
            MBAR_INIT(sb + SM_FULL + 8 * s, 64);   // 64 producer lanes
            MBAR_INIT(sb + SM_EMPTY + 8 * s, 8);   // 8 consumer warps
        }
    }
    if (tid < BM) {
        int r = row0 + tid;
        ridx[tid] = (r < n_rows) ? g_list[e][r] : -1;
    }
    __syncthreads();

    const __half* wh = g_wh + (size_t)e * OUT * IN;

    if (wid >= 8) {
        // ------------------- 2 producer warps -------------------
        const int plane = (wid - 8) * 32 + lane;   // 0..63
        const int ck = plane & 7;                  // 16B chunk in 128B row
        const int rg = plane >> 3;                 // 0..7
        int ph_empty[NSTAGE] = {0, 0, 0, 0};
        for (int c = 0; c < NCHUNK; c++) {
            const int st = c & (NSTAGE - 1);
            if (c >= NSTAGE) {
                MBAR_WAIT(sb + SM_EMPTY + 8 * st, ph_empty[st]);
                ph_empty[st] ^= 1;
            }
            const int k0 = c * BKC;
            const uint32_t stage = sb + SM_TILE + st * STAGE_BYTES;
            // A: 128 gathered rows, 16 per lane
#pragma unroll
            for (int i = 0; i < 16; i++) {
                const int m = i * 8 + rg;
                const int r = ridx[m];
                const size_t off = ((size_t)(r < 0 ? 0 : r) * IN + k0) * 2 + ck * 16;
                cp16(stage + OFF_A + sw_off(m, ck), (const char*)g_xh + off,
                     (r >= 0) ? 16 : 0);
            }
            // B: 256 contiguous rows, 32 per lane
#pragma unroll
            for (int i = 0; i < 32; i++) {
                const int n = i * 8 + rg;
                const size_t off = ((size_t)(col0 + n) * IN + k0) * 2 + ck * 16;
                cp16(stage + OFF_B + sw_off(n, ck), (const char*)wh + off, 16);
            }
            CPASYNC_MBAR_ARRIVE(sb + SM_FULL + 8 * st);
        }
        return;
    }

    // ------------------- consumer warps -------------------
    const int wm = wid & 1;      // m group: rows wm*64 .. wm*64+63
    const int wn = wid >> 1;     // n group: cols wn*64 .. wn*64+63

    float acc[4][8][4];
#pragma unroll
    for (int i = 0; i < 4; i++)
#pragma unroll
        for (int j = 0; j < 8; j++)
#pragma unroll
            for (int k = 0; k < 4; k++) acc[i][j][k] = 0.f;

    const int a_r = lane & 15;
    const int a_c = lane >> 4;
    const int b_r = ((lane >> 4) & 1) * 8 + (lane & 7);
    const int b_c = (lane >> 3) & 1;

    const int a_row0 = wm * 64 + a_r;
    const int b_row0 = wn * 64 + b_r;

    int ph_full[NSTAGE] = {0, 0, 0, 0};
    for (int c = 0; c < NCHUNK; c++) {
        const int st = c & (NSTAGE - 1);
        MBAR_WAIT(sb + SM_FULL + 8 * st, ph_full[st]);
        ph_full[st] ^= 1;

        const uint32_t stage = sb + SM_TILE + st * STAGE_BYTES;

        uint32_t ah[2][4][4];
        // preload A fragments for ks=0
#pragma unroll
        for (int i = 0; i < 4; i++)
            ldsm4(ah[0][i], stage + OFF_A + sw_off(a_row0 + i * 16, a_c));

#pragma unroll
        for (int ks = 0; ks < 4; ks++) {
            const int cur = ks & 1, nxt = cur ^ 1;
            // prefetch next ks's A fragments (issue under this ks's MMAs)
            if (ks < 3) {
#pragma unroll
                for (int i = 0; i < 4; i++)
                    ldsm4(ah[nxt][i],
                          stage + OFF_A + sw_off(a_row0 + i * 16, 2 * (ks + 1) + a_c));
            }
#pragma unroll
            for (int g = 0; g < 4; g++) {
                uint32_t bf[4];
                ldsm4(bf, stage + OFF_B + sw_off(b_row0 + g * 16, 2 * ks + b_c));
#pragma unroll
                for (int i = 0; i < 4; i++) {
                    mma16816(acc[i][2 * g],     ah[cur][i], &bf[0]);
                    mma16816(acc[i][2 * g + 1], ah[cur][i], &bf[2]);
                }
            }
        }
        __syncwarp();
        if (lane == 0) MBAR_ARRIVE(sb + SM_EMPTY + 8 * st);
    }

    // epilogue: store 0.5*(y + b_e) as fp16 to compacted scratch
    const float* bb = bias + (size_t)e * OUT + col0 + wn * 64 + 2 * (lane & 3);
#pragma unroll
    for (int i = 0; i < 4; i++) {
        int mbase = wm * 64 + i * 16 + (lane >> 2);
#pragma unroll
        for (int half = 0; half < 2; half++) {
            int mloc = mbase + half * 8;
            if (row0 + mloc < n_rows) {
                __half* yrow = g_yh + ((size_t)e * BATCH + row0 + mloc) * OUT
                             + col0 + wn * 64 + 2 * (lane & 3);
#pragma unroll
                for (int g = 0; g < 8; g++) {
                    float2 bv = *(const float2*)(bb + 8 * g);
                    __half2 h = __floats2half2_rn(
                        0.5f * (acc[i][g][2 * half] + bv.x),
                        0.5f * (acc[i][g][2 * half + 1] + bv.y));
                    *(__half2*)(yrow + 8 * g) = h;
                }
            }
        }
    }
}

// Combine: out[s] = yh[e1][p1] + yh[e2][p2]  (each already 0.5*(y+b)).
__global__ void combine_kernel(float* __restrict__ out) {
    const int s = blockIdx.x;
    const int4 sel = g_sel[s];
    const uint4* y1 = (const uint4*)(g_yh + ((size_t)sel.x * BATCH + sel.y) * OUT);
    const uint4* y2 = (const uint4*)(g_yh + ((size_t)sel.z * BATCH + sel.w) * OUT);
    float4* o = (float4*)(out + (size_t)s * OUT);
    const int i = threadIdx.x;           // 256 threads, OUT/8 = 256 groups of 8
    uint4 a = y1[i];
    uint4 b = y2[i];
    float4 r0, r1;
    {
        float2 fa = __half22float2(*(__half2*)&a.x), fb = __half22float2(*(__half2*)&b.x);
        r0.x = fa.x + fb.x; r0.y = fa.y + fb.y;
        fa = __half22float2(*(__half2*)&a.y); fb = __half22float2(*(__half2*)&b.y);
        r0.z = fa.x + fb.x; r0.w = fa.y + fb.y;
        fa = __half22float2(*(__half2*)&a.z); fb = __half22float2(*(__half2*)&b.z);
        r1.x = fa.x + fb.x; r1.y = fa.y + fb.y;
        fa = __half22float2(*(__half2*)&a.w); fb = __half22float2(*(__half2*)&b.w);
        r1.z = fa.x + fb.x; r1.w = fa.y + fb.y;
    }
    o[2 * i]     = r0;
    o[2 * i + 1] = r1;
}

// ---------------------------------------------------------------------------
extern "C" void kernel_launch(void* const* d_in, const int* in_sizes, int n_in,
                              void* d_out, int out_size) {
    const float* x  = (const float*)d_in[0];
    const float* W  = (const float*)d_in[1];
    const float* b  = (const float*)d_in[2];
    const float* Ws = (const float*)d_in[3];
    const float* bs = (const float*)d_in[4];
    float* out = (float*)d_out;

    static void* cnt_addr = nullptr;
    static bool attr_set = false;
    if (!attr_set) {
        cudaFuncSetAttribute(moe_gemm_kernel,
                             cudaFuncAttributeMaxDynamicSharedMemorySize, SMEM_TOTAL);
        cudaGetSymbolAddress(&cnt_addr, g_cnt);
        attr_set = true;
    }

    cudaMemsetAsync(cnt_addr, 0, P * sizeof(int));
    prep_kernel<<<PREP_BLOCKS, 256>>>(x, W, Ws, bs);   // selector + W conversion

    dim3 grid(OUT / BN, BATCH / BM, P);                // (8, 64, 8)
    moe_gemm_kernel<<<grid, NTHREADS, SMEM_TOTAL>>>(b);

    combine_kernel<<<BATCH, 256>>>(out);
}

// round 16
// speedup vs baseline: 1.1272x; 1.0690x over previous
#include <cuda_runtime.h>
#include <cuda_fp16.h>
#include <cstdint>

#define BATCH 8192
#define IN    2048
#define OUT   2048
#define P     8

#define BM 128
#define BN 256
#define BKC 64                 // fp16 K per chunk (128 B rows, xor-swizzled)
#define NCHUNK (IN / BKC)      // 32
#define NSTAGE 4

#define NTHREADS 320           // 8 consumer warps + 2 producer warps (reg cap 204)

// prep grid split (r11 static split — measured 62.9us)
#define SEL_BLOCKS 1024        // selector: one warp per sample
#define WCV_BLOCKS 2048        // W -> fp16 conversion
#define PREP_BLOCKS (SEL_BLOCKS + WCV_BLOCKS)

// ---- dynamic shared memory layout ----
#define SM_CNT    0            // 8 ints (expert counts snapshot)
#define SM_FULL   512          // 4 x 8B mbarriers
#define SM_EMPTY  576          // 4 x 8B mbarriers
#define SM_TILE   1024
#define OFF_A     0            // 128 rows x 128B = 16 KB
#define OFF_B     16384        // 256 rows x 128B = 32 KB
#define STAGE_BYTES 49152      // 48 KB per stage
#define SMEM_TOTAL (SM_TILE + NSTAGE * STAGE_BYTES)   // 197632 B

// ---------------- device scratch (no allocations allowed) ----------------
__device__ int  g_cnt[P];
__device__ int  g_list[P][BATCH];
__device__ int4 g_sel[BATCH];                      // e1,p1,e2,p2 per sample
__device__ __half g_xh[(size_t)BATCH * IN];        // 32 MB
__device__ __half g_wh[(size_t)P * OUT * IN];      // 64 MB
__device__ __half g_yh[(size_t)P * BATCH * OUT];   // 268 MB: 0.5*(y + b_e), fp16

// ---------------- helpers ----------------
__device__ __forceinline__ uint32_t smem_u32(const void* p) {
    uint32_t a;
    asm("{ .reg .u64 t; cvta.to.shared.u64 t, %1; cvt.u32.u64 %0, t; }"
        : "=r"(a) : "l"(p));
    return a;
}

__device__ __forceinline__ void cp16(uint32_t dst, const void* src, int sz) {
    asm volatile("cp.async.cg.shared.global [%0], [%1], 16, %2;"
                 :: "r"(dst), "l"(src), "r"(sz));
}

__device__ __forceinline__ void ldsm4(uint32_t* r, uint32_t addr) {
    asm volatile("ldmatrix.sync.aligned.m8n8.x4.shared.b16 {%0,%1,%2,%3}, [%4];"
                 : "=r"(r[0]), "=r"(r[1]), "=r"(r[2]), "=r"(r[3]) : "r"(addr));
}

__device__ __forceinline__ void mma16816(float* c, const uint32_t* a, const uint32_t* b) {
    asm volatile(
        "mma.sync.aligned.m16n8k16.row.col.f32.f16.f16.f32 "
        "{%0,%1,%2,%3}, {%4,%5,%6,%7}, {%8,%9}, {%0,%1,%2,%3};"
        : "+f"(c[0]), "+f"(c[1]), "+f"(c[2]), "+f"(c[3])
        : "r"(a[0]), "r"(a[1]), "r"(a[2]), "r"(a[3]), "r"(b[0]), "r"(b[1]));
}

#define MBAR_INIT(addr, cnt) \
    asm volatile("mbarrier.init.shared.b64 [%0], %1;" :: "r"(addr), "r"(cnt) : "memory")

#define MBAR_ARRIVE(addr) \
    asm volatile("mbarrier.arrive.shared.b64 _, [%0];" :: "r"(addr) : "memory")

#define CPASYNC_MBAR_ARRIVE(addr) \
    asm volatile("cp.async.mbarrier.arrive.noinc.shared.b64 [%0];" :: "r"(addr) : "memory")

#define MBAR_WAIT(addr, parity) do {                                              \
    asm volatile(                                                                 \
        "{\n\t.reg .pred P1;\n\t"                                                 \
        "WAIT_%=:\n\t"                                                            \
        "mbarrier.try_wait.parity.acquire.cta.shared::cta.b64 P1, [%0], %1, 0x989680;\n\t" \
        "@P1 bra.uni DONE_%=;\n\t"                                                \
        "bra.uni WAIT_%=;\n\t"                                                    \
        "DONE_%=:\n\t}"                                                           \
        :: "r"(addr), "r"(parity) : "memory");                                    \
} while (0)

// swizzled byte offset inside a [rows][128B] tile: 16B chunk index XOR (row & 7)
__device__ __forceinline__ uint32_t sw_off(int row, int chunk) {
    return (uint32_t)(row * 128 + ((chunk ^ (row & 7)) << 4));
}

// ---------------------------------------------------------------------------
// Merged prep kernel (r11 proven form): blocks [0, SEL_BLOCKS) selector,
// blocks [SEL_BLOCKS, PREP_BLOCKS) W -> fp16.
__global__ void prep_kernel(const float* __restrict__ x,
                            const float* __restrict__ W,
                            const float* __restrict__ Ws,
                            const float* __restrict__ bs) {
    if (blockIdx.x >= SEL_BLOCKS) {
        // ---- W -> fp16 ----
        const int bid = blockIdx.x - SEL_BLOCKS;
        size_t n4 = (size_t)P * OUT * IN / 4;
        size_t stride = (size_t)WCV_BLOCKS * blockDim.x;
        for (size_t i = (size_t)bid * blockDim.x + threadIdx.x; i < n4; i += stride) {
            float4 v = ((const float4*)W)[i];
            ((__half2*)g_wh)[2 * i]     = __floats2half2_rn(v.x, v.y);
            ((__half2*)g_wh)[2 * i + 1] = __floats2half2_rn(v.z, v.w);
        }
        return;
    }
    // ---- selector: top-2 of logits (softmax monotone -> skip), 1 warp/sample
    const int warp = threadIdx.x >> 5;
    const int lane = threadIdx.x & 31;
    const int s = blockIdx.x * (blockDim.x >> 5) + warp;   // 0..8191

    const float4* xr = (const float4*)(x + (size_t)s * IN);
    __half2* xh = (__half2*)(g_xh + (size_t)s * IN);
    float acc[P];
#pragma unroll
    for (int p = 0; p < P; p++) acc[p] = 0.f;
#pragma unroll
    for (int it = 0; it < IN / 128; it++) {            // 16 iterations
        const int k4 = it * 32 + lane;
        float4 xv = xr[k4];
        xh[2 * k4]     = __floats2half2_rn(xv.x, xv.y);
        xh[2 * k4 + 1] = __floats2half2_rn(xv.z, xv.w);
#pragma unroll
        for (int p = 0; p < P; p++) {
            float4 wv = ((const float4*)(Ws + (size_t)p * IN))[k4];
            acc[p] += xv.x * wv.x + xv.y * wv.y + xv.z * wv.z + xv.w * wv.w;
        }
    }
#pragma unroll
    for (int p = 0; p < P; p++) {
#pragma unroll
        for (int off = 16; off; off >>= 1)
            acc[p] += __shfl_xor_sync(0xffffffffu, acc[p], off);
    }
    if (lane == 0) {
        float best = -1e30f; int e1 = 0;
#pragma unroll
        for (int p = 0; p < P; p++) {
            float v = acc[p] + bs[p];
            acc[p] = v;
            if (v > best) { best = v; e1 = p; }
        }
        float sec = -1e30f; int e2 = 0;
#pragma unroll
        for (int p = 0; p < P; p++)
            if (p != e1 && acc[p] > sec) { sec = acc[p]; e2 = p; }
        int p1 = atomicAdd(&g_cnt[e1], 1);
        g_list[e1][p1] = s;
        int p2 = atomicAdd(&g_cnt[e2], 1);
        g_list[e2][p2] = s;
        g_sel[s] = make_int4(e1, p1, e2, p2);
    }
}

// ---------------------------------------------------------------------------
// PERSISTENT warp-specialized grouped gather-GEMM (r11 inner body, frozen).
// Grid = #SMs, 1 CTA/SM. Each CTA strides over the global tile list
// (expert-major: for e, row-tile, col-tile). The mbarrier ring runs
// CONTINUOUSLY across tiles: the producer fills tile t+1 while consumers
// finish tile t's MMAs + epilogue, hiding pipeline fill and epilogue time.
// ---------------------------------------------------------------------------
__global__ __launch_bounds__(NTHREADS, 1)
void moe_gemm_kernel(const float* __restrict__ bias) {
    extern __shared__ char smem[];
    const uint32_t sb = smem_u32(smem);
    int* scnt = (int*)(smem + SM_CNT);
    const int tid = threadIdx.x;
    const int lane = tid & 31;
    const int wid = tid >> 5;

    if (tid == 0) {
#pragma unroll
        for (int s = 0; s < NSTAGE; s++) {
            MBAR_INIT(sb + SM_FULL + 8 * s, 64);   // 64 producer lanes
            MBAR_INIT(sb + SM_EMPTY + 8 * s, 8);   // 8 consumer warps
        }
    }
    if (tid < P) scnt[tid] = g_cnt[tid];
    __syncthreads();

    // per-warp tile map: tiles_e = ceil(cnt_e/BM)*8, expert-major order
    int tcnt[P];
    int total = 0;
#pragma unroll
    for (int p = 0; p < P; p++) {
        tcnt[p] = ((scnt[p] + BM - 1) / BM) * 8;
        total += tcnt[p];
    }

    if (wid >= 8) {
        // ------------------- 2 producer warps -------------------
        const int plane = (wid - 8) * 32 + lane;   // 0..63
        const int ck = plane & 7;                  // 16B chunk in 128B row
        const int rg = plane >> 3;                 // 0..7
        int ph_empty[NSTAGE] = {0, 0, 0, 0};
        int gc = 0;                                // global chunk counter
        for (int t = blockIdx.x; t < total; t += gridDim.x) {
            // map t -> (e, row0, col0)
            int tt = t, e = 0;
            while (tt >= tcnt[e]) { tt -= tcnt[e]; e++; }
            const int row0 = (tt >> 3) * BM;
            const int col0 = (tt & 7) * BN;
            const int n_rows = scnt[e];
            const __half* wh = g_wh + (size_t)e * OUT * IN;
            // A row indices for this tile (registers, 16 per lane)
            int ridx[16];
#pragma unroll
            for (int i = 0; i < 16; i++) {
                const int r = row0 + i * 8 + rg;
                ridx[i] = (r < n_rows) ? g_list[e][r] : -1;
            }
            for (int c = 0; c < NCHUNK; c++, gc++) {
                const int st = gc & (NSTAGE - 1);
                if (gc >= NSTAGE) {
                    MBAR_WAIT(sb + SM_EMPTY + 8 * st, ph_empty[st]);
                    ph_empty[st] ^= 1;
                }
                const int k0 = c * BKC;
                const uint32_t stage = sb + SM_TILE + st * STAGE_BYTES;
                // A: 128 gathered rows, 16 per lane
#pragma unroll
                for (int i = 0; i < 16; i++) {
                    const int m = i * 8 + rg;
                    const int r = ridx[i];
                    const size_t off = ((size_t)(r < 0 ? 0 : r) * IN + k0) * 2 + ck * 16;
                    cp16(stage + OFF_A + sw_off(m, ck), (const char*)g_xh + off,
                         (r >= 0) ? 16 : 0);
                }
                // B: 256 contiguous rows, 32 per lane
#pragma unroll
                for (int i = 0; i < 32; i++) {
                    const int n = i * 8 + rg;
                    const size_t off = ((size_t)(col0 + n) * IN + k0) * 2 + ck * 16;
                    cp16(stage + OFF_B + sw_off(n, ck), (const char*)wh + off, 16);
                }
                CPASYNC_MBAR_ARRIVE(sb + SM_FULL + 8 * st);
            }
        }
        return;
    }

    // ------------------- consumer warps -------------------
    const int wm = wid & 1;      // m group: rows wm*64 .. wm*64+63
    const int wn = wid >> 1;     // n group: cols wn*64 .. wn*64+63

    const int a_r = lane & 15;
    const int a_c = lane >> 4;
    const int b_r = ((lane >> 4) & 1) * 8 + (lane & 7);
    const int b_c = (lane >> 3) & 1;

    const int a_row0 = wm * 64 + a_r;
    const int b_row0 = wn * 64 + b_r;

    int ph_full[NSTAGE] = {0, 0, 0, 0};
    int gc = 0;

    for (int t = blockIdx.x; t < total; t += gridDim.x) {
        int tt = t, e = 0;
        while (tt >= tcnt[e]) { tt -= tcnt[e]; e++; }
        const int row0 = (tt >> 3) * BM;
        const int col0 = (tt & 7) * BN;
        const int n_rows = scnt[e];

        float acc[4][8][4];
#pragma unroll
        for (int i = 0; i < 4; i++)
#pragma unroll
            for (int j = 0; j < 8; j++)
#pragma unroll
                for (int k = 0; k < 4; k++) acc[i][j][k] = 0.f;

        for (int c = 0; c < NCHUNK; c++, gc++) {
            const int st = gc & (NSTAGE - 1);
            MBAR_WAIT(sb + SM_FULL + 8 * st, ph_full[st]);
            ph_full[st] ^= 1;

            const uint32_t stage = sb + SM_TILE + st * STAGE_BYTES;

            uint32_t ah[2][4][4];
#pragma unroll
            for (int i = 0; i < 4; i++)
                ldsm4(ah[0][i], stage + OFF_A + sw_off(a_row0 + i * 16, a_c));

#pragma unroll
            for (int ks = 0; ks < 4; ks++) {
                const int cur = ks & 1, nxt = cur ^ 1;
                if (ks < 3) {
#pragma unroll
                    for (int i = 0; i < 4; i++)
                        ldsm4(ah[nxt][i],
                              stage + OFF_A + sw_off(a_row0 + i * 16, 2 * (ks + 1) + a_c));
                }
#pragma unroll
                for (int g = 0; g < 4; g++) {
                    uint32_t bf[4];
                    ldsm4(bf, stage + OFF_B + sw_off(b_row0 + g * 16, 2 * ks + b_c));
#pragma unroll
                    for (int i = 0; i < 4; i++) {
                        mma16816(acc[i][2 * g],     ah[cur][i], &bf[0]);
                        mma16816(acc[i][2 * g + 1], ah[cur][i], &bf[2]);
                    }
                }
            }
            __syncwarp();
            if (lane == 0) MBAR_ARRIVE(sb + SM_EMPTY + 8 * st);
        }

        // epilogue: store 0.5*(y + b_e) as fp16 to compacted scratch
        const float* bb = bias + (size_t)e * OUT + col0 + wn * 64 + 2 * (lane & 3);
#pragma unroll
        for (int i = 0; i < 4; i++) {
            int mbase = wm * 64 + i * 16 + (lane >> 2);
#pragma unroll
            for (int half = 0; half < 2; half++) {
                int mloc = mbase + half * 8;
                if (row0 + mloc < n_rows) {
                    __half* yrow = g_yh + ((size_t)e * BATCH + row0 + mloc) * OUT
                                 + col0 + wn * 64 + 2 * (lane & 3);
#pragma unroll
                    for (int g = 0; g < 8; g++) {
                        float2 bv = *(const float2*)(bb + 8 * g);
                        __half2 h = __floats2half2_rn(
                            0.5f * (acc[i][g][2 * half] + bv.x),
                            0.5f * (acc[i][g][2 * half + 1] + bv.y));
                        *(__half2*)(yrow + 8 * g) = h;
                    }
                }
            }
        }
    }
}

// Combine: out[s] = yh[e1][p1] + yh[e2][p2]  (each already 0.5*(y+b)).
__global__ void combine_kernel(float* __restrict__ out) {
    const int s = blockIdx.x;
    const int4 sel = g_sel[s];
    const uint4* y1 = (const uint4*)(g_yh + ((size_t)sel.x * BATCH + sel.y) * OUT);
    const uint4* y2 = (const uint4*)(g_yh + ((size_t)sel.z * BATCH + sel.w) * OUT);
    float4* o = (float4*)(out + (size_t)s * OUT);
    const int i = threadIdx.x;           // 256 threads, OUT/8 = 256 groups of 8
    uint4 a = y1[i];
    uint4 b = y2[i];
    float4 r0, r1;
    {
        float2 fa = __half22float2(*(__half2*)&a.x), fb = __half22float2(*(__half2*)&b.x);
        r0.x = fa.x + fb.x; r0.y = fa.y + fb.y;
        fa = __half22float2(*(__half2*)&a.y); fb = __half22float2(*(__half2*)&b.y);
        r0.z = fa.x + fb.x; r0.w = fa.y + fb.y;
        fa = __half22float2(*(__half2*)&a.z); fb = __half22float2(*(__half2*)&b.z);
        r1.x = fa.x + fb.x; r1.y = fa.y + fb.y;
        fa = __half22float2(*(__half2*)&a.w); fb = __half22float2(*(__half2*)&b.w);
        r1.z = fa.x + fb.x; r1.w = fa.y + fb.y;
    }
    o[2 * i]     = r0;
    o[2 * i + 1] = r1;
}

// ---------------------------------------------------------------------------
extern "C" void kernel_launch(void* const* d_in, const int* in_sizes, int n_in,
                              void* d_out, int out_size) {
    const float* x  = (const float*)d_in[0];
    const float* W  = (const float*)d_in[1];
    const float* b  = (const float*)d_in[2];
    const float* Ws = (const float*)d_in[3];
    const float* bs = (const float*)d_in[4];
    float* out = (float*)d_out;

    static void* cnt_addr = nullptr;
    static int nsm = 0;
    if (!nsm) {
        cudaFuncSetAttribute(moe_gemm_kernel,
                             cudaFuncAttributeMaxDynamicSharedMemorySize, SMEM_TOTAL);
        cudaGetSymbolAddress(&cnt_addr, g_cnt);
        int dev = 0;
        cudaGetDevice(&dev);
        cudaDeviceGetAttribute(&nsm, cudaDevAttrMultiProcessorCount, dev);
        if (nsm <= 0) nsm = 148;
    }

    cudaMemsetAsync(cnt_addr, 0, P * sizeof(int));
    prep_kernel<<<PREP_BLOCKS, 256>>>(x, W, Ws, bs);   // selector + W conversion

    moe_gemm_kernel<<<nsm, NTHREADS, SMEM_TOTAL>>>(b); // persistent, 1 CTA/SM

    combine_kernel<<<BATCH, 256>>>(out);
}